// round 10
// baseline (speedup 1.0000x reference)
#include <cuda_runtime.h>
#include <cuda_bf16.h>
#include <math.h>
#include <stdint.h>

// ---------------- problem constants ----------------
#define NP 16384            // H*W per batch
#define NB 2
#define PL (NB * NP)        // elems per channel (both batches)
#define KSPLIT 16

// ---- channel offsets inside the hi/lo mega-planes ----
#define CH_X     0
#define CH_F     192
#define CH_X1    384
#define CH_MT    576
#define CH_OUTD  768
#define CH_ATTIN 1152
#define CH_QKV0  1344
#define CH_QKV   1920
#define CH_OUTA  2496
#define CH_XMID  2688
#define CH_X2L   2880
#define CH_FM    3072
#define CH_XIN   3648
#define CH_DW    4800
#define CH_X2H   5376      // CH_DW + 576
#define CH_MT2   5952
#define CH_OUT2  6528
#define CH_GX    7680
#define CH_TOT   8256

__device__ __nv_bfloat16 g_hi[(size_t)CH_TOT * PL];
__device__ __nv_bfloat16 g_lo[(size_t)CH_TOT * PL];

// ---- weight offsets ----
#define WO_AMSK  0
#define WO_ACC   36864
#define WO_AFUS  184320
#define WO_AQKV  258048
#define WO_APROJ 368640
#define WO_FPM   405504
#define WO_FPI   516096
#define WO_FMSK  737280
#define WO_FCC   1069056
#define WO_FFUS  2396160
#define WO_FPO   3059712
#define WTOT     3170304
__device__ __nv_bfloat16 g_whi[WTOT];
__device__ __nv_bfloat16 g_wlo[WTOT];

__device__ float g_f32[1024 + KSPLIT * 12288];   // NRM(768) + S partials

// ================= helpers =================
__device__ __forceinline__ uint32_t smem_u32(const void* p) {
    uint32_t a;
    asm("{ .reg .u64 t; cvta.to.shared.u64 t, %1; cvt.u32.u64 %0, t; }"
        : "=r"(a) : "l"(p));
    return a;
}
__device__ __forceinline__ void ldsm4(uint32_t r[4], uint32_t a) {
    asm volatile("ldmatrix.sync.aligned.m8n8.x4.shared.b16 {%0,%1,%2,%3}, [%4];"
                 : "=r"(r[0]), "=r"(r[1]), "=r"(r[2]), "=r"(r[3]) : "r"(a));
}
__device__ __forceinline__ void ldsm4t(uint32_t r[4], uint32_t a) {
    asm volatile("ldmatrix.sync.aligned.m8n8.x4.trans.shared.b16 {%0,%1,%2,%3}, [%4];"
                 : "=r"(r[0]), "=r"(r[1]), "=r"(r[2]), "=r"(r[3]) : "r"(a));
}
__device__ __forceinline__ void cpasync16(uint32_t s, const void* g) {
    asm volatile("cp.async.ca.shared.global [%0], [%1], 16;" :: "r"(s), "l"(g));
}
#define CP_COMMIT() asm volatile("cp.async.commit_group;" ::: "memory")
#define CP_WAIT0()  asm volatile("cp.async.wait_group 0;" ::: "memory")
#define CP_WAIT1()  asm volatile("cp.async.wait_group 1;" ::: "memory")

__device__ __forceinline__ void mma16816(float c[4], const uint32_t a[4],
                                         const uint32_t b[2]) {
    asm volatile(
        "mma.sync.aligned.m16n8k16.row.col.f32.bf16.bf16.f32 "
        "{%0,%1,%2,%3},{%4,%5,%6,%7},{%8,%9},{%0,%1,%2,%3};"
        : "+f"(c[0]), "+f"(c[1]), "+f"(c[2]), "+f"(c[3])
        : "r"(a[0]), "r"(a[1]), "r"(a[2]), "r"(a[3]), "r"(b[0]), "r"(b[1]));
}
__device__ __forceinline__ float b2f(__nv_bfloat16 v) {
    return __uint_as_float(((uint32_t)__bfloat16_as_ushort(v)) << 16);
}
__device__ __forceinline__ float rdhl(size_t idx) {
    return b2f(g_hi[idx]) + b2f(g_lo[idx]);
}
__device__ __forceinline__ void wrhl(size_t idx, float v) {
    __nv_bfloat16 h = __float2bfloat16_rn(v);
    g_hi[idx] = h;
    g_lo[idx] = __float2bfloat16_rn(v - b2f(h));
}
__device__ __forceinline__ void hilo2(float v0, float v1, uint32_t& hp, uint32_t& lp) {
    __nv_bfloat16 h0 = __float2bfloat16_rn(v0);
    __nv_bfloat16 h1 = __float2bfloat16_rn(v1);
    float r0 = v0 - b2f(h0), r1 = v1 - b2f(h1);
    __nv_bfloat16 l0 = __float2bfloat16_rn(r0);
    __nv_bfloat16 l1 = __float2bfloat16_rn(r1);
    hp = ((uint32_t)__bfloat16_as_ushort(h1) << 16) | __bfloat16_as_ushort(h0);
    lp = ((uint32_t)__bfloat16_as_ushort(l1) << 16) | __bfloat16_as_ushort(l0);
}

// ================= converters =================
__global__ void cvt_w(const float* __restrict__ src, size_t dst, int n) {
    int i = blockIdx.x * 256 + threadIdx.x;
    if (i < n) {
        float v = src[i];
        __nv_bfloat16 h = __float2bfloat16_rn(v);
        g_whi[dst + i] = h;
        g_wlo[dst + i] = __float2bfloat16_rn(v - b2f(h));
    }
}
__global__ void cvt_act(const float* __restrict__ src, int C, size_t chBase) {
    int b = blockIdx.z, c = blockIdx.y;
    int p = blockIdx.x * 256 + threadIdx.x;
    float v = src[((size_t)b * C + c) * NP + p];
    wrhl((chBase + c) * (size_t)PL + (size_t)b * NP + p, v);
}

// ---- shared epilogue helpers ----
struct EpiArgs {
    size_t e1Off, e2Off, yOff;
    int mode, Chalf, Cout;
    float* Yf;
    size_t bofs;
    int b;
};
__device__ __forceinline__ void rd2g(size_t ch, int o, int p, size_t bofs,
                                     float& v0, float& v1) {
    size_t ix = (ch + o) * (size_t)PL + bofs + p;
    uint32_t hu = *(const uint32_t*)(g_hi + ix);
    uint32_t lu = *(const uint32_t*)(g_lo + ix);
    v0 = __uint_as_float(hu << 16) + __uint_as_float(lu << 16);
    v1 = __uint_as_float(hu & 0xffff0000u) + __uint_as_float(lu & 0xffff0000u);
}
__device__ __forceinline__ void emitg(const EpiArgs& ea, int o, int p,
                                      float d0, float d1) {
    if (o >= ea.Cout) return;
    float y0, y1;
    if (ea.mode == 0) { y0 = d0; y1 = d1; }
    else if (ea.mode == 1) {
        float e0, e1v; rd2g(ea.e1Off, o, p, ea.bofs, e0, e1v);
        y0 = d0 + e0; y1 = d1 + e1v;
    } else if (ea.mode == 2) {
        float b0, b1;
        if (o < ea.Chalf) rd2g(ea.e1Off, o, p, ea.bofs, b0, b1);
        else              rd2g(ea.e2Off, o - ea.Chalf, p, ea.bofs, b0, b1);
        y0 = d0 * b0 + b0; y1 = d1 * b1 + b1;
    } else {
        float r0, r1, x0, x1;
        rd2g(ea.e1Off, o, p, ea.bofs, r0, r1);
        rd2g(ea.e2Off, o, p, ea.bofs, x0, x1);
        r0 += d0; r1 += d1;
        float g0 = 0.5f * x0 * (1.f + erff(x0 * 0.70710678118654752f));
        float g1 = 0.5f * x1 * (1.f + erff(x1 * 0.70710678118654752f));
        y0 = g0 * r0; y1 = g1 * r1;
    }
    if (ea.Yf) {
        *(float2*)(ea.Yf + ((size_t)ea.b * ea.Cout + o) * NP + p) = make_float2(y0, y1);
    } else {
        uint32_t hp, lp; hilo2(y0, y1, hp, lp);
        size_t ix = (ea.yOff + o) * (size_t)PL + ea.bofs + p;
        *(uint32_t*)(g_hi + ix) = hp;
        *(uint32_t*)(g_lo + ix) = lp;
    }
}

// ================= HMMA GEMM 64x256 (2-stage, occ 2) =================
#define SMA_ROW 80
#define PL_A 5120              // 64*80
#define SMB_ROW 528
#define PL_B 16896             // 32*528
#define SOFF_B 10240           // 2*PL_A
#define BUFSZ 44032
#define GSMEM 88064

__global__ void __launch_bounds__(256, 2)
hmma_gemm(size_t wOff, int K, size_t aOff1, int K1, size_t aOff2,
          int Cout, size_t e1Off, size_t e2Off, size_t yOff,
          int mode, int Chalf, float* __restrict__ Yf)
{
    extern __shared__ char smem[];
    const uint32_t sb = smem_u32(smem);
    const int tid = threadIdx.x, wid = tid >> 5, lane = tid & 31;
    const int g = lane >> 2, tig = lane & 3;
    const int wm = wid & 1, wn = wid >> 1;
    const int b = blockIdx.z;
    const int p0 = blockIdx.x * 256;
    const int o0 = blockIdx.y * 64;
    const size_t bofs = (size_t)b * NP;

    uint32_t aSm[2];
    const __nv_bfloat16* aGp[2];
#pragma unroll
    for (int r = 0; r < 2; r++) {
        int idx = r * 256 + tid, plane = idx >> 8, rem = idx & 255;
        int row = rem >> 2, c16 = rem & 3;
        aSm[r] = plane * PL_A + row * SMA_ROW + c16 * 16;
        aGp[r] = (plane ? g_wlo : g_whi) + wOff + (size_t)(o0 + row) * K + c16 * 8;
    }
    uint32_t bSm[8];
    int bKrow[8], bPlane[8], bCol[8];
#pragma unroll
    for (int r = 0; r < 8; r++) {
        int idx = r * 256 + tid, plane = idx >> 10, rem = idx & 1023;
        int krow = rem >> 5, c16 = rem & 31;
        bSm[r] = SOFF_B + plane * PL_B + krow * SMB_ROW + c16 * 16;
        bKrow[r] = krow; bPlane[r] = plane; bCol[r] = p0 + c16 * 8;
    }

    auto issue = [&](int kc, int buf) {
        uint32_t base = sb + buf * BUFSZ;
#pragma unroll
        for (int r = 0; r < 2; r++)
            cpasync16(base + aSm[r], aGp[r] + kc);
#pragma unroll
        for (int r = 0; r < 8; r++) {
            int kg = kc + bKrow[r];
            size_t ch = (kg < K1) ? (aOff1 + kg) : (aOff2 + (kg - K1));
            const __nv_bfloat16* src = (bPlane[r] ? g_lo : g_hi)
                                     + ch * (size_t)PL + bofs + bCol[r];
            cpasync16(base + bSm[r], src);
        }
        CP_COMMIT();
    };

    const uint32_t offAt = (uint32_t)(lane & 15) * SMA_ROW + (uint32_t)(lane >> 4) * 16
                         + (uint32_t)(wm * 32) * SMA_ROW;
    const uint32_t offBt = (uint32_t)((lane & 7) + ((lane >> 3) & 1) * 8) * SMB_ROW
                         + (uint32_t)(lane >> 4) * 16;

    float acc[2][8][4];
#pragma unroll
    for (int i = 0; i < 2; i++)
#pragma unroll
        for (int j = 0; j < 8; j++)
#pragma unroll
            for (int q = 0; q < 4; q++) acc[i][j][q] = 0.f;

    const int nch = K >> 5;
    issue(0, 0);
    CP_WAIT0();
    __syncthreads();

    for (int c = 0; c < nch; c++) {
        const bool more = (c + 1 < nch);
        if (more) issue((c + 1) * 32, (c + 1) & 1);

        uint32_t base = sb + (c & 1) * BUFSZ;
        uint32_t aH = base + offAt, aL = aH + PL_A;
        uint32_t bH = base + SOFF_B + offBt, bL = bH + PL_B;
#pragma unroll
        for (int s = 0; s < 2; s++) {
            uint32_t ah[2][4], al[2][4];
#pragma unroll
            for (int i = 0; i < 2; i++) {
                ldsm4(ah[i], aH + i * (16 * SMA_ROW) + s * 32);
                ldsm4(al[i], aL + i * (16 * SMA_ROW) + s * 32);
            }
#pragma unroll
            for (int t = 0; t < 4; t++) {
                uint32_t bh4[4], bl4[4];
                uint32_t bo = s * (16 * SMB_ROW) + (uint32_t)(wn * 64 + t * 16) * 2;
                ldsm4t(bh4, bH + bo);
                ldsm4t(bl4, bL + bo);
#pragma unroll
                for (int jj = 0; jj < 2; jj++) {
                    int j = t * 2 + jj;
                    const uint32_t* bhf = &bh4[jj * 2];
                    const uint32_t* blf = &bl4[jj * 2];
#pragma unroll
                    for (int i = 0; i < 2; i++) {
                        mma16816(acc[i][j], ah[i], bhf);
                        mma16816(acc[i][j], al[i], bhf);
                        mma16816(acc[i][j], ah[i], blf);
                    }
                }
            }
        }
        if (more) CP_WAIT0();
        __syncthreads();
    }

    EpiArgs ea{e1Off, e2Off, yOff, mode, Chalf, Cout, Yf, bofs, b};
    const int obase = o0 + wm * 32;
    const int pbase = p0 + wn * 64;
#pragma unroll
    for (int i = 0; i < 2; i++) {
#pragma unroll
        for (int j = 0; j < 8; j++) {
            int oA = obase + i * 16 + g;
            int p  = pbase + j * 8 + tig * 2;
            emitg(ea, oA,     p, acc[i][j][0], acc[i][j][1]);
            emitg(ea, oA + 8, p, acc[i][j][2], acc[i][j][3]);
        }
    }
}

// ================= HMMA GEMM 128x256 (3-stage, warp 64x64) =================
// For Cout % 128 == 0. 8 warps = 2(M) x 4(N), warp tile 64x64.
#define PLA2 10240             // 128*80
#define SOFFB2 20480           // 2*PLA2
#define STAGE2 54272           // 2*PLA2 + 2*PL_B
#define GSMEM2 162816          // 3 stages

__global__ void __launch_bounds__(256, 1)
hmma_gemm128(size_t wOff, int K, size_t aOff1, int K1, size_t aOff2,
             int Cout, size_t e1Off, size_t e2Off, size_t yOff,
             int mode, int Chalf, float* __restrict__ Yf)
{
    extern __shared__ char smem[];
    const uint32_t sb = smem_u32(smem);
    const int tid = threadIdx.x, wid = tid >> 5, lane = tid & 31;
    const int g = lane >> 2, tig = lane & 3;
    const int wm = wid & 1, wn = wid >> 1;
    const int b = blockIdx.z;
    const int p0 = blockIdx.x * 256;
    const int o0 = blockIdx.y * 128;
    const size_t bofs = (size_t)b * NP;

    // A: 128 rows x 32k x 2 planes = 1024 cp.async -> 4/thread
    uint32_t aSm[4];
    const __nv_bfloat16* aGp[4];
#pragma unroll
    for (int r = 0; r < 4; r++) {
        int idx = r * 256 + tid, plane = idx >> 9, rem = idx & 511;
        int row = rem >> 2, c16 = rem & 3;
        aSm[r] = plane * PLA2 + row * SMA_ROW + c16 * 16;
        int orow = o0 + row; if (orow >= Cout) orow = Cout - 1;
        aGp[r] = (plane ? g_wlo : g_whi) + wOff + (size_t)orow * K + c16 * 8;
    }
    uint32_t bSm[8];
    int bKrow[8], bPlane[8], bCol[8];
#pragma unroll
    for (int r = 0; r < 8; r++) {
        int idx = r * 256 + tid, plane = idx >> 10, rem = idx & 1023;
        int krow = rem >> 5, c16 = rem & 31;
        bSm[r] = SOFFB2 + plane * PL_B + krow * SMB_ROW + c16 * 16;
        bKrow[r] = krow; bPlane[r] = plane; bCol[r] = p0 + c16 * 8;
    }

    auto issue = [&](int kc, int buf) {
        uint32_t base = sb + buf * STAGE2;
#pragma unroll
        for (int r = 0; r < 4; r++)
            cpasync16(base + aSm[r], aGp[r] + kc);
#pragma unroll
        for (int r = 0; r < 8; r++) {
            int kg = kc + bKrow[r];
            size_t ch = (kg < K1) ? (aOff1 + kg) : (aOff2 + (kg - K1));
            const __nv_bfloat16* src = (bPlane[r] ? g_lo : g_hi)
                                     + ch * (size_t)PL + bofs + bCol[r];
            cpasync16(base + bSm[r], src);
        }
        CP_COMMIT();
    };

    const uint32_t offAt = (uint32_t)(lane & 15) * SMA_ROW + (uint32_t)(lane >> 4) * 16
                         + (uint32_t)(wm * 64) * SMA_ROW;
    const uint32_t offBt = (uint32_t)((lane & 7) + ((lane >> 3) & 1) * 8) * SMB_ROW
                         + (uint32_t)(lane >> 4) * 16;

    float acc[4][8][4];
#pragma unroll
    for (int i = 0; i < 4; i++)
#pragma unroll
        for (int j = 0; j < 8; j++)
#pragma unroll
            for (int q = 0; q < 4; q++) acc[i][j][q] = 0.f;

    const int nch = K >> 5;
    issue(0, 0);
    if (nch > 1) issue(32, 1);

    for (int c = 0; c < nch; c++) {
        if (c + 1 < nch) { CP_WAIT1(); } else { CP_WAIT0(); }
        __syncthreads();
        if (c + 2 < nch) issue((c + 2) * 32, (c + 2) % 3);

        uint32_t base = sb + (c % 3) * STAGE2;
        uint32_t aH = base + offAt, aL = aH + PLA2;
        uint32_t bH = base + SOFFB2 + offBt, bL = bH + PL_B;
#pragma unroll
        for (int s = 0; s < 2; s++) {
            uint32_t ah[4][4], al[4][4];
#pragma unroll
            for (int i = 0; i < 4; i++) {
                ldsm4(ah[i], aH + i * (16 * SMA_ROW) + s * 32);
                ldsm4(al[i], aL + i * (16 * SMA_ROW) + s * 32);
            }
#pragma unroll
            for (int t = 0; t < 4; t++) {
                uint32_t bh4[4], bl4[4];
                uint32_t bo = s * (16 * SMB_ROW) + (uint32_t)(wn * 64 + t * 16) * 2;
                ldsm4t(bh4, bH + bo);
                ldsm4t(bl4, bL + bo);
#pragma unroll
                for (int jj = 0; jj < 2; jj++) {
                    int j = t * 2 + jj;
                    const uint32_t* bhf = &bh4[jj * 2];
                    const uint32_t* blf = &bl4[jj * 2];
#pragma unroll
                    for (int i = 0; i < 4; i++) {
                        mma16816(acc[i][j], ah[i], bhf);
                        mma16816(acc[i][j], al[i], bhf);
                        mma16816(acc[i][j], ah[i], blf);
                    }
                }
            }
        }
        __syncthreads();
    }

    EpiArgs ea{e1Off, e2Off, yOff, mode, Chalf, Cout, Yf, bofs, b};
    const int obase = o0 + wm * 64;
    const int pbase = p0 + wn * 64;
#pragma unroll
    for (int i = 0; i < 4; i++) {
#pragma unroll
        for (int j = 0; j < 8; j++) {
            int oA = obase + i * 16 + g;
            int p  = pbase + j * 8 + tig * 2;
            emitg(ea, oA,     p, acc[i][j][0], acc[i][j][1]);
            emitg(ea, oA + 8, p, acc[i][j][2], acc[i][j][3]);
        }
    }
}

// ---------------- LayerNorm (fp32 in -> hl out) ----------------
__global__ void ln_f32(const float* __restrict__ in, const float* __restrict__ g,
                       const float* __restrict__ be, size_t dstCh)
{
    int b = blockIdx.y;
    int p = blockIdx.x * 256 + threadIdx.x;
    const float* ib = in + (size_t)b * 192 * NP + p;
    float s = 0.f, ss = 0.f;
    for (int c = 0; c < 192; c++) {
        float v = ib[(size_t)c * NP];
        s += v; ss += v * v;
    }
    float mu = s / 192.f;
    float var = ss / 192.f - mu * mu;
    float rstd = rsqrtf(var + 1e-5f);
    size_t ob = dstCh * (size_t)PL + (size_t)b * NP + p;
    for (int c = 0; c < 192; c++) {
        float v = ib[(size_t)c * NP];
        wrhl(ob + (size_t)c * PL, (v - mu) * rstd * g[c] + be[c]);
    }
}
__global__ void ln_hl(size_t srcCh, const float* __restrict__ g,
                      const float* __restrict__ be, size_t dstCh)
{
    int b = blockIdx.y;
    int p = blockIdx.x * 256 + threadIdx.x;
    size_t ibase = srcCh * (size_t)PL + (size_t)b * NP + p;
    float s = 0.f, ss = 0.f;
    for (int c = 0; c < 192; c++) {
        float v = rdhl(ibase + (size_t)c * PL);
        s += v; ss += v * v;
    }
    float mu = s / 192.f;
    float var = ss / 192.f - mu * mu;
    float rstd = rsqrtf(var + 1e-5f);
    size_t ob = dstCh * (size_t)PL + (size_t)b * NP + p;
    for (int c = 0; c < 192; c++) {
        float v = rdhl(ibase + (size_t)c * PL);
        wrhl(ob + (size_t)c * PL, (v - mu) * rstd * g[c] + be[c]);
    }
}

// ---------------- depthwise 3x3 (hl -> hl) ----------------
__global__ void dw_hl(size_t srcCh, const float* __restrict__ w, size_t dstCh, int C)
{
    int b = blockIdx.z, c = blockIdx.y;
    int p = blockIdx.x * 256 + threadIdx.x;
    int y = p >> 7, x = p & 127;
    size_t ib = (srcCh + c) * (size_t)PL + (size_t)b * NP;
    const float* wc = w + c * 9;
    float acc = 0.f;
#pragma unroll
    for (int dy = -1; dy <= 1; dy++) {
        int yy = y + dy;
        if (yy < 0 || yy > 127) continue;
#pragma unroll
        for (int dx = -1; dx <= 1; dx++) {
            int xx = x + dx;
            if (xx < 0 || xx > 127) continue;
            acc = fmaf(rdhl(ib + yy * 128 + xx), wc[(dy + 1) * 3 + (dx + 1)], acc);
        }
    }
    wrhl((dstCh + c) * (size_t)PL + (size_t)b * NP + p, acc);
}

// ---------------- row L2 norms of q,k ----------------
__global__ void norm_kernel(float* __restrict__ nrm)
{
    int r = blockIdx.x;              // 0..767
    int b = r / 384, c = r % 384;
    size_t src = (CH_QKV + c) * (size_t)PL + (size_t)b * NP;
    float s = 0.f;
    for (int i = threadIdx.x; i < NP; i += 256) {
        float v = rdhl(src + i);
        s += v * v;
    }
    __shared__ float red[256];
    red[threadIdx.x] = s;
    __syncthreads();
    for (int st = 128; st > 0; st >>= 1) {
        if (threadIdx.x < st) red[threadIdx.x] += red[threadIdx.x + st];
        __syncthreads();
    }
    if (threadIdx.x == 0) nrm[r] = fmaxf(sqrtf(red[0]), 1e-12f);
}

// ---------------- attention scores ----------------
__global__ void scores_kernel(float* __restrict__ S)
{
    int bh = blockIdx.x;
    int ks = blockIdx.y;
    int b = bh / 6, h = bh % 6;
    size_t qb = (CH_QKV + h * 32) * (size_t)PL + (size_t)b * NP;
    size_t kb = (CH_QKV + 192 + h * 32) * (size_t)PL + (size_t)b * NP;
    __shared__ float qs[32][65], ksm[32][65];
    int tid = threadIdx.x;
    int c = tid >> 3, d0 = (tid & 7) * 4;
    float acc[4] = {0.f, 0.f, 0.f, 0.f};
    int kbase = ks * (NP / KSPLIT);
    for (int t = 0; t < (NP / KSPLIT) / 64; t++) {
        int k0 = kbase + t * 64;
#pragma unroll
        for (int i = 0; i < 8; i++) {
            int e = tid + i * 256;
            int row = e >> 6, col = e & 63;
            qs[row][col]  = rdhl(qb + (size_t)row * PL + k0 + col);
            ksm[row][col] = rdhl(kb + (size_t)row * PL + k0 + col);
        }
        __syncthreads();
#pragma unroll
        for (int kk = 0; kk < 64; kk++) {
            float qv = qs[c][kk];
#pragma unroll
            for (int j = 0; j < 4; j++)
                acc[j] = fmaf(qv, ksm[d0 + j][kk], acc[j]);
        }
        __syncthreads();
    }
    float* Sp = S + (size_t)ks * 12288 + bh * 1024 + c * 32 + d0;
#pragma unroll
    for (int j = 0; j < 4; j++) Sp[j] = acc[j];
}

// ---------------- softmax with norm + temperature ----------------
__global__ void softmax_kernel(float* __restrict__ S, const float* __restrict__ nrm,
                               const float* __restrict__ temp)
{
    int bh = blockIdx.y;
    int c  = blockIdx.x;
    int b = bh / 6, h = bh % 6;
    int d = threadIdx.x;
    float acc = 0.f;
    size_t idx = (size_t)bh * 1024 + c * 32 + d;
    for (int j = 0; j < KSPLIT; j++) acc += S[(size_t)j * 12288 + idx];
    float nq = nrm[b * 384 + h * 32 + c];
    float nk = nrm[b * 384 + 192 + h * 32 + d];
    float v = acc / (nq * nk) * temp[h];
    float m = v;
    for (int o = 16; o; o >>= 1) m = fmaxf(m, __shfl_xor_sync(0xffffffffu, m, o));
    float e = expf(v - m);
    float s = e;
    for (int o = 16; o; o >>= 1) s += __shfl_xor_sync(0xffffffffu, s, o);
    S[idx] = e / s;
}

// ---------------- out = attn @ v (hl in, hl out) ----------------
__global__ void av_kernel(const float* __restrict__ S)
{
    int b = blockIdx.z, h = blockIdx.y;
    int p = blockIdx.x * 128 + threadIdx.x;
    __shared__ float A[32][32];
    int bh = b * 6 + h;
    for (int i = threadIdx.x; i < 1024; i += 128)
        A[i >> 5][i & 31] = S[(size_t)bh * 1024 + i];
    __syncthreads();
    size_t vb = (CH_QKV + 384 + h * 32) * (size_t)PL + (size_t)b * NP + p;
    float vr[32];
#pragma unroll
    for (int d = 0; d < 32; d++) vr[d] = rdhl(vb + (size_t)d * PL);
    size_t ob = (CH_OUTA + h * 32) * (size_t)PL + (size_t)b * NP + p;
#pragma unroll
    for (int c = 0; c < 32; c++) {
        float acc = 0.f;
#pragma unroll
        for (int d = 0; d < 32; d++) acc = fmaf(A[c][d], vr[d], acc);
        wrhl(ob + (size_t)c * PL, acc);
    }
}

// ---------------- host orchestration ----------------
static inline void launch_gemm(size_t wOff, int K, size_t aOff1, int K1, size_t aOff2,
                               int Cout, size_t e1Off, size_t e2Off, size_t yOff,
                               int mode, int Chalf, float* Yf)
{
    if (Cout % 128 == 0) {
        dim3 grid(NP / 256, Cout / 128, NB);
        hmma_gemm128<<<grid, 256, GSMEM2>>>(wOff, K, aOff1, K1, aOff2, Cout,
                                            e1Off, e2Off, yOff, mode, Chalf, Yf);
    } else {
        dim3 grid(NP / 256, Cout / 64, NB);
        hmma_gemm<<<grid, 256, GSMEM>>>(wOff, K, aOff1, K1, aOff2, Cout,
                                        e1Off, e2Off, yOff, mode, Chalf, Yf);
    }
}

extern "C" void kernel_launch(void* const* d_in, const int* in_sizes, int n_in,
                              void* d_out, int out_size)
{
    const float* x       = (const float*)d_in[0];
    const float* feature = (const float*)d_in[1];
    const float* nf_w = (const float*)d_in[2];
    const float* nf_b = (const float*)d_in[3];
    const float* n1_w = (const float*)d_in[4];
    const float* n1_b = (const float*)d_in[5];
    const float* n2_w = (const float*)d_in[6];
    const float* n2_b = (const float*)d_in[7];
    const float* a_cc_w   = (const float*)d_in[8];
    const float* a_fus_w  = (const float*)d_in[9];
    const float* a_msk_w  = (const float*)d_in[10];
    const float* a_qkv_w  = (const float*)d_in[11];
    const float* a_qkvdw  = (const float*)d_in[12];
    const float* a_temp   = (const float*)d_in[13];
    const float* a_proj_w = (const float*)d_in[14];
    const float* f_pm_w   = (const float*)d_in[15];
    const float* f_pi_w   = (const float*)d_in[16];
    const float* f_dw_w   = (const float*)d_in[17];
    const float* f_cc_w   = (const float*)d_in[18];
    const float* f_fus_w  = (const float*)d_in[19];
    const float* f_msk_w  = (const float*)d_in[20];
    const float* f_po_w   = (const float*)d_in[21];
    float* out = (float*)d_out;

    cudaFuncSetAttribute(hmma_gemm, cudaFuncAttributeMaxDynamicSharedMemorySize, GSMEM);
    cudaFuncSetAttribute(hmma_gemm128, cudaFuncAttributeMaxDynamicSharedMemorySize, GSMEM2);

    float* f32 = nullptr;
    cudaGetSymbolAddress((void**)&f32, g_f32);
    float* NRM = f32;
    float* S   = f32 + 1024;

    auto cw = [&](const float* src, size_t off, int n) {
        cvt_w<<<(n + 255) / 256, 256>>>(src, off, n);
    };
    cw(a_msk_w,  WO_AMSK,  36864);
    cw(a_cc_w,   WO_ACC,   147456);
    cw(a_fus_w,  WO_AFUS,  73728);
    cw(a_qkv_w,  WO_AQKV,  110592);
    cw(a_proj_w, WO_APROJ, 36864);
    cw(f_pm_w,   WO_FPM,   110592);
    cw(f_pi_w,   WO_FPI,   221184);
    cw(f_msk_w,  WO_FMSK,  331776);
    cw(f_cc_w,   WO_FCC,   1327104);
    cw(f_fus_w,  WO_FFUS,  663552);
    cw(f_po_w,   WO_FPO,   110592);
    cvt_act<<<dim3(NP / 256, 192, NB), 256>>>(x, 192, CH_X);

    dim3 lng(NP / 256, NB);
    ln_f32<<<lng, 256>>>(feature, nf_w, nf_b, CH_F);
    ln_f32<<<lng, 256>>>(x, n1_w, n1_b, CH_X1);

    // --- attention DDF ---
    launch_gemm(WO_AMSK, 192, CH_F, 192, CH_F, 192, 0, 0, CH_MT, 0, 0, nullptr);
    launch_gemm(WO_ACC, 384, CH_X1, 192, CH_MT, 384, CH_X1, CH_MT, CH_OUTD, 2, 192, nullptr);
    launch_gemm(WO_AFUS, 384, CH_OUTD, 384, CH_OUTD, 192, CH_X1, 0, CH_ATTIN, 1, 0, nullptr);

    // qkv + depthwise
    launch_gemm(WO_AQKV, 192, CH_ATTIN, 192, CH_ATTIN, 576, 0, 0, CH_QKV0, 0, 0, nullptr);
    dw_hl<<<dim3(NP / 256, 576, NB), 256>>>(CH_QKV0, a_qkvdw, CH_QKV, 576);

    // channel attention
    norm_kernel<<<768, 256>>>(NRM);
    scores_kernel<<<dim3(12, KSPLIT), 256>>>(S);
    softmax_kernel<<<dim3(32, 12), 32>>>(S, NRM, a_temp);
    av_kernel<<<dim3(NP / 128, 6, NB), 128>>>(S);

    // proj + residual with original x
    launch_gemm(WO_APROJ, 192, CH_OUTA, 192, CH_OUTA, 192, CH_X, 0, CH_XMID, 1, 0, nullptr);

    // --- FFN ---
    ln_hl<<<lng, 256>>>(CH_XMID, n2_w, n2_b, CH_X2L);
    launch_gemm(WO_FPM, 192, CH_F, 192, CH_F, 576, 0, 0, CH_FM, 0, 0, nullptr);
    launch_gemm(WO_FPI, 192, CH_X2L, 192, CH_X2L, 1152, 0, 0, CH_XIN, 0, 0, nullptr);
    dw_hl<<<dim3(NP / 256, 1152, NB), 256>>>(CH_XIN, f_dw_w, CH_DW, 1152);

    launch_gemm(WO_FMSK, 576, CH_FM, 576, CH_FM, 576, 0, 0, CH_MT2, 0, 0, nullptr);
    launch_gemm(WO_FCC, 1152, CH_X2H, 576, CH_MT2, 1152, CH_X2H, CH_MT2, CH_OUT2, 2, 576, nullptr);
    launch_gemm(WO_FFUS, 1152, CH_OUT2, 1152, CH_OUT2, 576, CH_X2H, CH_DW, CH_GX, 3, 0, nullptr);
    launch_gemm(WO_FPO, 576, CH_GX, 576, CH_GX, 192, CH_XMID, 0, 0, 1, 0, out);
}

// round 12
// speedup vs baseline: 1.6340x; 1.6340x over previous
#include <cuda_runtime.h>
#include <cuda_bf16.h>
#include <math.h>
#include <stdint.h>

// ---------------- problem constants ----------------
#define NP 16384            // H*W per batch
#define NB 2
#define PL (NB * NP)        // elems per channel (both batches)
#define KSPLIT 16

// ---- channel offsets inside the hi/lo mega-planes ----
#define CH_F     192
#define CH_X1    384
#define CH_MT    576
#define CH_OUTD  768
#define CH_ATTIN 1152
#define CH_QKV0  1344
#define CH_QKV   1920
#define CH_OUTA  2496
#define CH_XMID  2688
#define CH_X2L   2880
#define CH_FM    3072
#define CH_XIN   3648
#define CH_DW    4800
#define CH_X2H   5376      // CH_DW + 576
#define CH_MT2   5952
#define CH_OUT2  6528
#define CH_GX    7680
#define CH_TOT   8256

__device__ __nv_bfloat16 g_hi[(size_t)CH_TOT * PL];
__device__ __nv_bfloat16 g_lo[(size_t)CH_TOT * PL];

// ---- weight offsets ----
#define WO_AMSK  0
#define WO_ACC   36864
#define WO_AFUS  184320
#define WO_AQKV  258048
#define WO_APROJ 368640
#define WO_FPM   405504
#define WO_FPI   516096
#define WO_FMSK  737280
#define WO_FCC   1069056
#define WO_FFUS  2396160
#define WO_FPO   3059712
#define WTOT     3170304
__device__ __nv_bfloat16 g_whi[WTOT];
__device__ __nv_bfloat16 g_wlo[WTOT];

__device__ float g_f32[1024 + KSPLIT * 12288];   // NRM(768) + S partials

// ================= helpers =================
__device__ __forceinline__ uint32_t smem_u32(const void* p) {
    uint32_t a;
    asm("{ .reg .u64 t; cvta.to.shared.u64 t, %1; cvt.u32.u64 %0, t; }"
        : "=r"(a) : "l"(p));
    return a;
}
__device__ __forceinline__ void ldsm4(uint32_t r[4], uint32_t a) {
    asm volatile("ldmatrix.sync.aligned.m8n8.x4.shared.b16 {%0,%1,%2,%3}, [%4];"
                 : "=r"(r[0]), "=r"(r[1]), "=r"(r[2]), "=r"(r[3]) : "r"(a));
}
__device__ __forceinline__ void ldsm4t(uint32_t r[4], uint32_t a) {
    asm volatile("ldmatrix.sync.aligned.m8n8.x4.trans.shared.b16 {%0,%1,%2,%3}, [%4];"
                 : "=r"(r[0]), "=r"(r[1]), "=r"(r[2]), "=r"(r[3]) : "r"(a));
}
__device__ __forceinline__ void cpasync16(uint32_t s, const void* g) {
    asm volatile("cp.async.ca.shared.global [%0], [%1], 16;" :: "r"(s), "l"(g));
}
#define CP_COMMIT() asm volatile("cp.async.commit_group;" ::: "memory")
#define CP_WAIT0()  asm volatile("cp.async.wait_group 0;" ::: "memory")

__device__ __forceinline__ void mma16816(float c[4], const uint32_t a[4],
                                         const uint32_t b[2]) {
    asm volatile(
        "mma.sync.aligned.m16n8k16.row.col.f32.bf16.bf16.f32 "
        "{%0,%1,%2,%3},{%4,%5,%6,%7},{%8,%9},{%0,%1,%2,%3};"
        : "+f"(c[0]), "+f"(c[1]), "+f"(c[2]), "+f"(c[3])
        : "r"(a[0]), "r"(a[1]), "r"(a[2]), "r"(a[3]), "r"(b[0]), "r"(b[1]));
}
__device__ __forceinline__ float b2f(__nv_bfloat16 v) {
    return __uint_as_float(((uint32_t)__bfloat16_as_ushort(v)) << 16);
}
__device__ __forceinline__ float rdhl(size_t idx) {
    return b2f(g_hi[idx]) + b2f(g_lo[idx]);
}
__device__ __forceinline__ void wrhl(size_t idx, float v) {
    __nv_bfloat16 h = __float2bfloat16_rn(v);
    g_hi[idx] = h;
    g_lo[idx] = __float2bfloat16_rn(v - b2f(h));
}
__device__ __forceinline__ void hilo2(float v0, float v1, uint32_t& hp, uint32_t& lp) {
    __nv_bfloat16 h0 = __float2bfloat16_rn(v0);
    __nv_bfloat16 h1 = __float2bfloat16_rn(v1);
    float r0 = v0 - b2f(h0), r1 = v1 - b2f(h1);
    __nv_bfloat16 l0 = __float2bfloat16_rn(r0);
    __nv_bfloat16 l1 = __float2bfloat16_rn(r1);
    hp = ((uint32_t)__bfloat16_as_ushort(h1) << 16) | __bfloat16_as_ushort(h0);
    lp = ((uint32_t)__bfloat16_as_ushort(l1) << 16) | __bfloat16_as_ushort(l0);
}

// ================= converters =================
__global__ void cvt_w(const float* __restrict__ src, size_t dst, int n) {
    int i = blockIdx.x * 256 + threadIdx.x;
    if (i < n) {
        float v = src[i];
        __nv_bfloat16 h = __float2bfloat16_rn(v);
        g_whi[dst + i] = h;
        g_wlo[dst + i] = __float2bfloat16_rn(v - b2f(h));
    }
}

// ---- shared epilogue helpers ----
struct EpiArgs {
    size_t e1Off, e2Off, yOff;
    int mode, Chalf, Cout;
    float* Yf;
    const float* e1f;     // if non-null: mode-1 residual read from fp32 [b,C,NP]
    size_t bofs;
    int b;
};
__device__ __forceinline__ void rd2g(size_t ch, int o, int p, size_t bofs,
                                     float& v0, float& v1) {
    size_t ix = (ch + o) * (size_t)PL + bofs + p;
    uint32_t hu = *(const uint32_t*)(g_hi + ix);
    uint32_t lu = *(const uint32_t*)(g_lo + ix);
    v0 = __uint_as_float(hu << 16) + __uint_as_float(lu << 16);
    v1 = __uint_as_float(hu & 0xffff0000u) + __uint_as_float(lu & 0xffff0000u);
}
__device__ __forceinline__ void emitg(const EpiArgs& ea, int o, int p,
                                      float d0, float d1) {
    if (o >= ea.Cout) return;
    float y0, y1;
    if (ea.mode == 0) { y0 = d0; y1 = d1; }
    else if (ea.mode == 1) {
        float e0, e1v;
        if (ea.e1f) {
            float2 e = *(const float2*)(ea.e1f + ((size_t)ea.b * ea.Cout + o) * NP + p);
            e0 = e.x; e1v = e.y;
        } else {
            rd2g(ea.e1Off, o, p, ea.bofs, e0, e1v);
        }
        y0 = d0 + e0; y1 = d1 + e1v;
    } else if (ea.mode == 2) {
        float b0, b1;
        if (o < ea.Chalf) rd2g(ea.e1Off, o, p, ea.bofs, b0, b1);
        else              rd2g(ea.e2Off, o - ea.Chalf, p, ea.bofs, b0, b1);
        y0 = d0 * b0 + b0; y1 = d1 * b1 + b1;
    } else {
        float r0, r1, x0, x1;
        rd2g(ea.e1Off, o, p, ea.bofs, r0, r1);
        rd2g(ea.e2Off, o, p, ea.bofs, x0, x1);
        r0 += d0; r1 += d1;
        float g0 = 0.5f * x0 * (1.f + erff(x0 * 0.70710678118654752f));
        float g1 = 0.5f * x1 * (1.f + erff(x1 * 0.70710678118654752f));
        y0 = g0 * r0; y1 = g1 * r1;
    }
    if (ea.Yf) {
        *(float2*)(ea.Yf + ((size_t)ea.b * ea.Cout + o) * NP + p) = make_float2(y0, y1);
    } else {
        uint32_t hp, lp; hilo2(y0, y1, hp, lp);
        size_t ix = (ea.yOff + o) * (size_t)PL + ea.bofs + p;
        *(uint32_t*)(g_hi + ix) = hp;
        *(uint32_t*)(g_lo + ix) = lp;
    }
}

// ================= HMMA GEMM 64x256 (2-stage, occ 2) =================
#define SMA_ROW 80
#define PL_A 5120              // 64*80
#define SMB_ROW 528
#define PL_B 16896             // 32*528
#define SOFF_B 10240           // 2*PL_A
#define BUFSZ 44032
#define GSMEM 88064

__global__ void __launch_bounds__(256, 2)
hmma_gemm(size_t wOff, int K, size_t aOff1, int K1, size_t aOff2,
          int Cout, size_t e1Off, size_t e2Off, size_t yOff,
          int mode, int Chalf, float* __restrict__ Yf,
          const float* __restrict__ E1f)
{
    extern __shared__ char smem[];
    const uint32_t sb = smem_u32(smem);
    const int tid = threadIdx.x, wid = tid >> 5, lane = tid & 31;
    const int g = lane >> 2, tig = lane & 3;
    const int wm = wid & 1, wn = wid >> 1;
    const int b = blockIdx.z;
    const int p0 = blockIdx.x * 256;
    const int o0 = blockIdx.y * 64;
    const size_t bofs = (size_t)b * NP;

    uint32_t aSm[2];
    const __nv_bfloat16* aGp[2];
#pragma unroll
    for (int r = 0; r < 2; r++) {
        int idx = r * 256 + tid, plane = idx >> 8, rem = idx & 255;
        int row = rem >> 2, c16 = rem & 3;
        aSm[r] = plane * PL_A + row * SMA_ROW + c16 * 16;
        aGp[r] = (plane ? g_wlo : g_whi) + wOff + (size_t)(o0 + row) * K + c16 * 8;
    }
    uint32_t bSm[8];
    int bKrow[8], bPlane[8], bCol[8];
#pragma unroll
    for (int r = 0; r < 8; r++) {
        int idx = r * 256 + tid, plane = idx >> 10, rem = idx & 1023;
        int krow = rem >> 5, c16 = rem & 31;
        bSm[r] = SOFF_B + plane * PL_B + krow * SMB_ROW + c16 * 16;
        bKrow[r] = krow; bPlane[r] = plane; bCol[r] = p0 + c16 * 8;
    }

    auto issue = [&](int kc, int buf) {
        uint32_t base = sb + buf * BUFSZ;
#pragma unroll
        for (int r = 0; r < 2; r++)
            cpasync16(base + aSm[r], aGp[r] + kc);
#pragma unroll
        for (int r = 0; r < 8; r++) {
            int kg = kc + bKrow[r];
            size_t ch = (kg < K1) ? (aOff1 + kg) : (aOff2 + (kg - K1));
            const __nv_bfloat16* src = (bPlane[r] ? g_lo : g_hi)
                                     + ch * (size_t)PL + bofs + bCol[r];
            cpasync16(base + bSm[r], src);
        }
        CP_COMMIT();
    };

    const uint32_t offAt = (uint32_t)(lane & 15) * SMA_ROW + (uint32_t)(lane >> 4) * 16
                         + (uint32_t)(wm * 32) * SMA_ROW;
    const uint32_t offBt = (uint32_t)((lane & 7) + ((lane >> 3) & 1) * 8) * SMB_ROW
                         + (uint32_t)(lane >> 4) * 16;

    float acc[2][8][4];
#pragma unroll
    for (int i = 0; i < 2; i++)
#pragma unroll
        for (int j = 0; j < 8; j++)
#pragma unroll
            for (int q = 0; q < 4; q++) acc[i][j][q] = 0.f;

    const int nch = K >> 5;
    issue(0, 0);
    CP_WAIT0();
    __syncthreads();

    for (int c = 0; c < nch; c++) {
        const bool more = (c + 1 < nch);
        if (more) issue((c + 1) * 32, (c + 1) & 1);

        uint32_t base = sb + (c & 1) * BUFSZ;
        uint32_t aH = base + offAt, aL = aH + PL_A;
        uint32_t bH = base + SOFF_B + offBt, bL = bH + PL_B;
#pragma unroll
        for (int s = 0; s < 2; s++) {
            uint32_t ah[2][4], al[2][4];
#pragma unroll
            for (int i = 0; i < 2; i++) {
                ldsm4(ah[i], aH + i * (16 * SMA_ROW) + s * 32);
                ldsm4(al[i], aL + i * (16 * SMA_ROW) + s * 32);
            }
#pragma unroll
            for (int t = 0; t < 4; t++) {
                uint32_t bh4[4], bl4[4];
                uint32_t bo = s * (16 * SMB_ROW) + (uint32_t)(wn * 64 + t * 16) * 2;
                ldsm4t(bh4, bH + bo);
                ldsm4t(bl4, bL + bo);
#pragma unroll
                for (int jj = 0; jj < 2; jj++) {
                    int j = t * 2 + jj;
                    const uint32_t* bhf = &bh4[jj * 2];
                    const uint32_t* blf = &bl4[jj * 2];
#pragma unroll
                    for (int i = 0; i < 2; i++) {
                        mma16816(acc[i][j], ah[i], bhf);
                        mma16816(acc[i][j], al[i], bhf);
                        mma16816(acc[i][j], ah[i], blf);
                    }
                }
            }
        }
        if (more) CP_WAIT0();
        __syncthreads();
    }

    EpiArgs ea{e1Off, e2Off, yOff, mode, Chalf, Cout, Yf, E1f, bofs, b};
    const int obase = o0 + wm * 32;
    const int pbase = p0 + wn * 64;
#pragma unroll
    for (int i = 0; i < 2; i++) {
#pragma unroll
        for (int j = 0; j < 8; j++) {
            int oA = obase + i * 16 + g;
            int p  = pbase + j * 8 + tig * 2;
            emitg(ea, oA,     p, acc[i][j][0], acc[i][j][1]);
            emitg(ea, oA + 8, p, acc[i][j][2], acc[i][j][3]);
        }
    }
}

// ---------------- LayerNorm (fp32 in -> hl out) ----------------
__global__ void ln_f32(const float* __restrict__ in, const float* __restrict__ g,
                       const float* __restrict__ be, size_t dstCh)
{
    int b = blockIdx.y;
    int p = blockIdx.x * 256 + threadIdx.x;
    const float* ib = in + (size_t)b * 192 * NP + p;
    float s = 0.f, ss = 0.f;
    for (int c = 0; c < 192; c++) {
        float v = ib[(size_t)c * NP];
        s += v; ss += v * v;
    }
    float mu = s / 192.f;
    float var = ss / 192.f - mu * mu;
    float rstd = rsqrtf(var + 1e-5f);
    size_t ob = dstCh * (size_t)PL + (size_t)b * NP + p;
    for (int c = 0; c < 192; c++) {
        float v = ib[(size_t)c * NP];
        wrhl(ob + (size_t)c * PL, (v - mu) * rstd * g[c] + be[c]);
    }
}
__global__ void ln_hl(size_t srcCh, const float* __restrict__ g,
                      const float* __restrict__ be, size_t dstCh)
{
    int b = blockIdx.y;
    int p = blockIdx.x * 256 + threadIdx.x;
    size_t ibase = srcCh * (size_t)PL + (size_t)b * NP + p;
    float s = 0.f, ss = 0.f;
    for (int c = 0; c < 192; c++) {
        float v = rdhl(ibase + (size_t)c * PL);
        s += v; ss += v * v;
    }
    float mu = s / 192.f;
    float var = ss / 192.f - mu * mu;
    float rstd = rsqrtf(var + 1e-5f);
    size_t ob = dstCh * (size_t)PL + (size_t)b * NP + p;
    for (int c = 0; c < 192; c++) {
        float v = rdhl(ibase + (size_t)c * PL);
        wrhl(ob + (size_t)c * PL, (v - mu) * rstd * g[c] + be[c]);
    }
}

// ---------------- depthwise 3x3 (hl -> hl), smem-tiled ----------------
// block = 256 thr = 2 output rows x 128 cols; grid (64, C, NB)
__global__ void dw_hl(size_t srcCh, const float* __restrict__ w, size_t dstCh, int C)
{
    __shared__ float tile[4][128];
    int b = blockIdx.z, c = blockIdx.y;
    int y0 = blockIdx.x * 2;
    int tr = threadIdx.x >> 7;          // 0..1
    int tx = threadIdx.x & 127;
    size_t ib = (srcCh + c) * (size_t)PL + (size_t)b * NP;
#pragma unroll
    for (int r = tr; r < 4; r += 2) {
        int yy = y0 - 1 + r;
        tile[r][tx] = (yy >= 0 && yy < 128) ? rdhl(ib + yy * 128 + tx) : 0.f;
    }
    __syncthreads();
    const float* wc = w + c * 9;
    float acc = 0.f;
#pragma unroll
    for (int dy = 0; dy < 3; dy++) {
        int r = tr + dy;
#pragma unroll
        for (int dx = -1; dx <= 1; dx++) {
            int xx = tx + dx;
            if (xx < 0 || xx > 127) continue;
            acc = fmaf(tile[r][xx], wc[dy * 3 + dx + 1], acc);
        }
    }
    int y = y0 + tr;
    wrhl((dstCh + c) * (size_t)PL + (size_t)b * NP + y * 128 + tx, acc);
}

// ---------------- row L2 norms of q,k ----------------
__global__ void norm_kernel(float* __restrict__ nrm)
{
    int r = blockIdx.x;              // 0..767
    int b = r / 384, c = r % 384;
    size_t src = (CH_QKV + c) * (size_t)PL + (size_t)b * NP;
    float s = 0.f;
    for (int i = threadIdx.x; i < NP; i += 256) {
        float v = rdhl(src + i);
        s += v * v;
    }
    __shared__ float red[256];
    red[threadIdx.x] = s;
    __syncthreads();
    for (int st = 128; st > 0; st >>= 1) {
        if (threadIdx.x < st) red[threadIdx.x] += red[threadIdx.x + st];
        __syncthreads();
    }
    if (threadIdx.x == 0) nrm[r] = fmaxf(sqrtf(red[0]), 1e-12f);
}

// ---------------- attention scores ----------------
__global__ void scores_kernel(float* __restrict__ S)
{
    int bh = blockIdx.x;
    int ks = blockIdx.y;
    int b = bh / 6, h = bh % 6;
    size_t qb = (CH_QKV + h * 32) * (size_t)PL + (size_t)b * NP;
    size_t kb = (CH_QKV + 192 + h * 32) * (size_t)PL + (size_t)b * NP;
    __shared__ float qs[32][65], ksm[32][65];
    int tid = threadIdx.x;
    int c = tid >> 3, d0 = (tid & 7) * 4;
    float acc[4] = {0.f, 0.f, 0.f, 0.f};
    int kbase = ks * (NP / KSPLIT);
    for (int t = 0; t < (NP / KSPLIT) / 64; t++) {
        int k0 = kbase + t * 64;
#pragma unroll
        for (int i = 0; i < 8; i++) {
            int e = tid + i * 256;
            int row = e >> 6, col = e & 63;
            qs[row][col]  = rdhl(qb + (size_t)row * PL + k0 + col);
            ksm[row][col] = rdhl(kb + (size_t)row * PL + k0 + col);
        }
        __syncthreads();
#pragma unroll
        for (int kk = 0; kk < 64; kk++) {
            float qv = qs[c][kk];
#pragma unroll
            for (int j = 0; j < 4; j++)
                acc[j] = fmaf(qv, ksm[d0 + j][kk], acc[j]);
        }
        __syncthreads();
    }
    float* Sp = S + (size_t)ks * 12288 + bh * 1024 + c * 32 + d0;
#pragma unroll
    for (int j = 0; j < 4; j++) Sp[j] = acc[j];
}

// ---------------- softmax with norm + temperature ----------------
__global__ void softmax_kernel(float* __restrict__ S, const float* __restrict__ nrm,
                               const float* __restrict__ temp)
{
    int bh = blockIdx.y;
    int c  = blockIdx.x;
    int b = bh / 6, h = bh % 6;
    int d = threadIdx.x;
    float acc = 0.f;
    size_t idx = (size_t)bh * 1024 + c * 32 + d;
    for (int j = 0; j < KSPLIT; j++) acc += S[(size_t)j * 12288 + idx];
    float nq = nrm[b * 384 + h * 32 + c];
    float nk = nrm[b * 384 + 192 + h * 32 + d];
    float v = acc / (nq * nk) * temp[h];
    float m = v;
    for (int o = 16; o; o >>= 1) m = fmaxf(m, __shfl_xor_sync(0xffffffffu, m, o));
    float e = expf(v - m);
    float s = e;
    for (int o = 16; o; o >>= 1) s += __shfl_xor_sync(0xffffffffu, s, o);
    S[idx] = e / s;
}

// ---------------- out = attn @ v (hl in, hl out) ----------------
__global__ void av_kernel(const float* __restrict__ S)
{
    int b = blockIdx.z, h = blockIdx.y;
    int p = blockIdx.x * 128 + threadIdx.x;
    __shared__ float A[32][32];
    int bh = b * 6 + h;
    for (int i = threadIdx.x; i < 1024; i += 128)
        A[i >> 5][i & 31] = S[(size_t)bh * 1024 + i];
    __syncthreads();
    size_t vb = (CH_QKV + 384 + h * 32) * (size_t)PL + (size_t)b * NP + p;
    float vr[32];
#pragma unroll
    for (int d = 0; d < 32; d++) vr[d] = rdhl(vb + (size_t)d * PL);
    size_t ob = (CH_OUTA + h * 32) * (size_t)PL + (size_t)b * NP + p;
#pragma unroll
    for (int c = 0; c < 32; c++) {
        float acc = 0.f;
#pragma unroll
        for (int d = 0; d < 32; d++) acc = fmaf(A[c][d], vr[d], acc);
        wrhl(ob + (size_t)c * PL, acc);
    }
}

// ---------------- host orchestration ----------------
static inline void launch_gemm(size_t wOff, int K, size_t aOff1, int K1, size_t aOff2,
                               int Cout, size_t e1Off, size_t e2Off, size_t yOff,
                               int mode, int Chalf, float* Yf,
                               const float* E1f = nullptr)
{
    dim3 grid(NP / 256, Cout / 64, NB);
    hmma_gemm<<<grid, 256, GSMEM>>>(wOff, K, aOff1, K1, aOff2, Cout,
                                    e1Off, e2Off, yOff, mode, Chalf, Yf, E1f);
}

extern "C" void kernel_launch(void* const* d_in, const int* in_sizes, int n_in,
                              void* d_out, int out_size)
{
    const float* x       = (const float*)d_in[0];
    const float* feature = (const float*)d_in[1];
    const float* nf_w = (const float*)d_in[2];
    const float* nf_b = (const float*)d_in[3];
    const float* n1_w = (const float*)d_in[4];
    const float* n1_b = (const float*)d_in[5];
    const float* n2_w = (const float*)d_in[6];
    const float* n2_b = (const float*)d_in[7];
    const float* a_cc_w   = (const float*)d_in[8];
    const float* a_fus_w  = (const float*)d_in[9];
    const float* a_msk_w  = (const float*)d_in[10];
    const float* a_qkv_w  = (const float*)d_in[11];
    const float* a_qkvdw  = (const float*)d_in[12];
    const float* a_temp   = (const float*)d_in[13];
    const float* a_proj_w = (const float*)d_in[14];
    const float* f_pm_w   = (const float*)d_in[15];
    const float* f_pi_w   = (const float*)d_in[16];
    const float* f_dw_w   = (const float*)d_in[17];
    const float* f_cc_w   = (const float*)d_in[18];
    const float* f_fus_w  = (const float*)d_in[19];
    const float* f_msk_w  = (const float*)d_in[20];
    const float* f_po_w   = (const float*)d_in[21];
    float* out = (float*)d_out;

    cudaFuncSetAttribute(hmma_gemm, cudaFuncAttributeMaxDynamicSharedMemorySize, GSMEM);

    float* f32 = nullptr;
    cudaGetSymbolAddress((void**)&f32, g_f32);
    float* NRM = f32;
    float* S   = f32 + 1024;

    auto cw = [&](const float* src, size_t off, int n) {
        cvt_w<<<(n + 255) / 256, 256>>>(src, off, n);
    };
    cw(a_msk_w,  WO_AMSK,  36864);
    cw(a_cc_w,   WO_ACC,   147456);
    cw(a_fus_w,  WO_AFUS,  73728);
    cw(a_qkv_w,  WO_AQKV,  110592);
    cw(a_proj_w, WO_APROJ, 36864);
    cw(f_pm_w,   WO_FPM,   110592);
    cw(f_pi_w,   WO_FPI,   221184);
    cw(f_msk_w,  WO_FMSK,  331776);
    cw(f_cc_w,   WO_FCC,   1327104);
    cw(f_fus_w,  WO_FFUS,  663552);
    cw(f_po_w,   WO_FPO,   110592);

    dim3 lng(NP / 256, NB);
    ln_f32<<<lng, 256>>>(feature, nf_w, nf_b, CH_F);
    ln_f32<<<lng, 256>>>(x, n1_w, n1_b, CH_X1);

    // --- attention DDF ---
    launch_gemm(WO_AMSK, 192, CH_F, 192, CH_F, 192, 0, 0, CH_MT, 0, 0, nullptr);
    launch_gemm(WO_ACC, 384, CH_X1, 192, CH_MT, 384, CH_X1, CH_MT, CH_OUTD, 2, 192, nullptr);
    launch_gemm(WO_AFUS, 384, CH_OUTD, 384, CH_OUTD, 192, CH_X1, 0, CH_ATTIN, 1, 0, nullptr);

    // qkv + depthwise
    launch_gemm(WO_AQKV, 192, CH_ATTIN, 192, CH_ATTIN, 576, 0, 0, CH_QKV0, 0, 0, nullptr);
    dw_hl<<<dim3(64, 576, NB), 256>>>(CH_QKV0, a_qkvdw, CH_QKV, 576);

    // channel attention
    norm_kernel<<<768, 256>>>(NRM);
    scores_kernel<<<dim3(12, KSPLIT), 256>>>(S);
    softmax_kernel<<<dim3(32, 12), 32>>>(S, NRM, a_temp);
    av_kernel<<<dim3(NP / 128, 6, NB), 128>>>(S);

    // proj + residual with original fp32 x (read directly in epilogue)
    launch_gemm(WO_APROJ, 192, CH_OUTA, 192, CH_OUTA, 192, 0, 0, CH_XMID, 1, 0,
                nullptr, x);

    // --- FFN ---
    ln_hl<<<lng, 256>>>(CH_XMID, n2_w, n2_b, CH_X2L);
    launch_gemm(WO_FPM, 192, CH_F, 192, CH_F, 576, 0, 0, CH_FM, 0, 0, nullptr);
    launch_gemm(WO_FPI, 192, CH_X2L, 192, CH_X2L, 1152, 0, 0, CH_XIN, 0, 0, nullptr);
    dw_hl<<<dim3(64, 1152, NB), 256>>>(CH_XIN, f_dw_w, CH_DW, 1152);

    launch_gemm(WO_FMSK, 576, CH_FM, 576, CH_FM, 576, 0, 0, CH_MT2, 0, 0, nullptr);
    launch_gemm(WO_FCC, 1152, CH_X2H, 576, CH_MT2, 1152, CH_X2H, CH_MT2, CH_OUT2, 2, 576, nullptr);
    launch_gemm(WO_FFUS, 1152, CH_OUT2, 1152, CH_OUT2, 576, CH_X2H, CH_DW, CH_GX, 3, 0, nullptr);
    launch_gemm(WO_FPO, 576, CH_GX, 576, CH_GX, 192, CH_XMID, 0, 0, 1, 0, out);
}

// round 13
// speedup vs baseline: 1.9530x; 1.1953x over previous
#include <cuda_runtime.h>
#include <cuda_fp16.h>
#include <math.h>
#include <stdint.h>

// ---------------- problem constants ----------------
#define NP 16384            // H*W per batch
#define NB 2
#define PL (NB * NP)        // elems per channel (both batches)
#define KSPLIT 16

// ---- channel offsets inside the hi/lo mega-planes ----
#define CH_F     192
#define CH_X1    384
#define CH_MT    576
#define CH_OUTD  768
#define CH_ATTIN 1152
#define CH_QKV0  1344
#define CH_QKV   1920
#define CH_OUTA  2496
#define CH_XMID  2688
#define CH_X2L   2880
#define CH_FM    3072
#define CH_XIN   3648
#define CH_DW    4800
#define CH_X2H   5376      // CH_DW + 576
#define CH_MT2   5952
#define CH_OUT2  6528
#define CH_GX    7680
#define CH_TOT   8256

__device__ __half g_hi[(size_t)CH_TOT * PL];
__device__ __half g_lo[(size_t)CH_TOT * PL];

// ---- weight offsets (single fp16 plane) ----
#define WO_AMSK  0
#define WO_ACC   36864
#define WO_AFUS  184320
#define WO_AQKV  258048
#define WO_APROJ 368640
#define WO_FPM   405504
#define WO_FPI   516096
#define WO_FMSK  737280
#define WO_FCC   1069056
#define WO_FFUS  2396160
#define WO_FPO   3059712
#define WTOT     3170304
__device__ __half g_wh[WTOT];

__device__ float g_f32[1024 + KSPLIT * 12288];   // NRM(768) + S partials

// ================= helpers =================
__device__ __forceinline__ uint32_t smem_u32(const void* p) {
    uint32_t a;
    asm("{ .reg .u64 t; cvta.to.shared.u64 t, %1; cvt.u32.u64 %0, t; }"
        : "=r"(a) : "l"(p));
    return a;
}
__device__ __forceinline__ void ldsm4(uint32_t r[4], uint32_t a) {
    asm volatile("ldmatrix.sync.aligned.m8n8.x4.shared.b16 {%0,%1,%2,%3}, [%4];"
                 : "=r"(r[0]), "=r"(r[1]), "=r"(r[2]), "=r"(r[3]) : "r"(a));
}
__device__ __forceinline__ void ldsm4t(uint32_t r[4], uint32_t a) {
    asm volatile("ldmatrix.sync.aligned.m8n8.x4.trans.shared.b16 {%0,%1,%2,%3}, [%4];"
                 : "=r"(r[0]), "=r"(r[1]), "=r"(r[2]), "=r"(r[3]) : "r"(a));
}
__device__ __forceinline__ void cpasync16(uint32_t s, const void* g) {
    asm volatile("cp.async.ca.shared.global [%0], [%1], 16;" :: "r"(s), "l"(g));
}
#define CP_COMMIT() asm volatile("cp.async.commit_group;" ::: "memory")
#define CP_WAIT0()  asm volatile("cp.async.wait_group 0;" ::: "memory")

__device__ __forceinline__ void mma16816(float c[4], const uint32_t a[4],
                                         const uint32_t b[2]) {
    asm volatile(
        "mma.sync.aligned.m16n8k16.row.col.f32.f16.f16.f32 "
        "{%0,%1,%2,%3},{%4,%5,%6,%7},{%8,%9},{%0,%1,%2,%3};"
        : "+f"(c[0]), "+f"(c[1]), "+f"(c[2]), "+f"(c[3])
        : "r"(a[0]), "r"(a[1]), "r"(a[2]), "r"(a[3]), "r"(b[0]), "r"(b[1]));
}
__device__ __forceinline__ float rdhl(size_t idx) {
    return __half2float(g_hi[idx]) + __half2float(g_lo[idx]);
}
__device__ __forceinline__ void wrhl(size_t idx, float v) {
    __half h = __float2half_rn(v);
    g_hi[idx] = h;
    g_lo[idx] = __float2half_rn(v - __half2float(h));
}
// fp32 pair -> packed fp16 hi pair + lo pair (first elem in low bits)
__device__ __forceinline__ void hilo2(float v0, float v1, uint32_t& hp, uint32_t& lp) {
    __half h0 = __float2half_rn(v0);
    __half h1 = __float2half_rn(v1);
    __half l0 = __float2half_rn(v0 - __half2float(h0));
    __half l1 = __float2half_rn(v1 - __half2float(h1));
    hp = ((uint32_t)__half_as_ushort(h1) << 16) | __half_as_ushort(h0);
    lp = ((uint32_t)__half_as_ushort(l1) << 16) | __half_as_ushort(l0);
}

// ================= converters =================
__global__ void cvt_w(const float* __restrict__ src, size_t dst, int n) {
    int i = blockIdx.x * 256 + threadIdx.x;
    if (i < n) g_wh[dst + i] = __float2half_rn(src[i]);
}

// ---- shared epilogue helpers ----
struct EpiArgs {
    size_t e1Off, e2Off, yOff;
    int mode, Chalf, Cout;
    float* Yf;
    const float* e1f;     // if non-null: mode-1 residual read from fp32 [b,C,NP]
    size_t bofs;
    int b;
};
__device__ __forceinline__ void rd2g(size_t ch, int o, int p, size_t bofs,
                                     float& v0, float& v1) {
    size_t ix = (ch + o) * (size_t)PL + bofs + p;
    __half2 h2 = *(const __half2*)(g_hi + ix);
    __half2 l2 = *(const __half2*)(g_lo + ix);
    v0 = __half2float(__low2half(h2))  + __half2float(__low2half(l2));
    v1 = __half2float(__high2half(h2)) + __half2float(__high2half(l2));
}
__device__ __forceinline__ void emitg(const EpiArgs& ea, int o, int p,
                                      float d0, float d1) {
    if (o >= ea.Cout) return;
    float y0, y1;
    if (ea.mode == 0) { y0 = d0; y1 = d1; }
    else if (ea.mode == 1) {
        float e0, e1v;
        if (ea.e1f) {
            float2 e = *(const float2*)(ea.e1f + ((size_t)ea.b * ea.Cout + o) * NP + p);
            e0 = e.x; e1v = e.y;
        } else {
            rd2g(ea.e1Off, o, p, ea.bofs, e0, e1v);
        }
        y0 = d0 + e0; y1 = d1 + e1v;
    } else if (ea.mode == 2) {
        float b0, b1;
        if (o < ea.Chalf) rd2g(ea.e1Off, o, p, ea.bofs, b0, b1);
        else              rd2g(ea.e2Off, o - ea.Chalf, p, ea.bofs, b0, b1);
        y0 = d0 * b0 + b0; y1 = d1 * b1 + b1;
    } else {
        float r0, r1, x0, x1;
        rd2g(ea.e1Off, o, p, ea.bofs, r0, r1);
        rd2g(ea.e2Off, o, p, ea.bofs, x0, x1);
        r0 += d0; r1 += d1;
        float g0 = 0.5f * x0 * (1.f + erff(x0 * 0.70710678118654752f));
        float g1 = 0.5f * x1 * (1.f + erff(x1 * 0.70710678118654752f));
        y0 = g0 * r0; y1 = g1 * r1;
    }
    if (ea.Yf) {
        *(float2*)(ea.Yf + ((size_t)ea.b * ea.Cout + o) * NP + p) = make_float2(y0, y1);
    } else {
        uint32_t hp, lp; hilo2(y0, y1, hp, lp);
        size_t ix = (ea.yOff + o) * (size_t)PL + ea.bofs + p;
        *(uint32_t*)(g_hi + ix) = hp;
        *(uint32_t*)(g_lo + ix) = lp;
    }
}

// ================= HMMA GEMM 64x256 (2-stage, occ 2, fp16 2-MMA) =================
// A: 1 fp16 plane (weights). B: 2 fp16 planes (act hi/lo).
#define SMA_ROW 80
#define PL_A 5120              // 64*80
#define SMB_ROW 528
#define PL_B 16896             // 32*528
#define SOFF_B PL_A            // 5120
#define BUFSZ (PL_A + 2 * PL_B)   // 38912
#define GSMEM (2 * BUFSZ)         // 77824

__global__ void __launch_bounds__(256, 2)
hmma_gemm(size_t wOff, int K, size_t aOff1, int K1, size_t aOff2,
          int Cout, size_t e1Off, size_t e2Off, size_t yOff,
          int mode, int Chalf, float* __restrict__ Yf,
          const float* __restrict__ E1f)
{
    extern __shared__ char smem[];
    const uint32_t sb = smem_u32(smem);
    const int tid = threadIdx.x, wid = tid >> 5, lane = tid & 31;
    const int g = lane >> 2, tig = lane & 3;
    const int wm = wid & 1, wn = wid >> 1;
    const int b = blockIdx.z;
    const int p0 = blockIdx.x * 256;
    const int o0 = blockIdx.y * 64;
    const size_t bofs = (size_t)b * NP;

    // A cp.async: 1 op/thread (64 rows x 4 c16)
    const int aRow = tid >> 2, aC16 = tid & 3;
    const uint32_t aSm = aRow * SMA_ROW + aC16 * 16;
    const __half* aGp = g_wh + wOff + (size_t)(o0 + aRow) * K + aC16 * 8;

    // B cp.async: 8 ops/thread
    uint32_t bSm[8];
    int bKrow[8], bPlane[8], bCol[8];
#pragma unroll
    for (int r = 0; r < 8; r++) {
        int idx = r * 256 + tid, plane = idx >> 10, rem = idx & 1023;
        int krow = rem >> 5, c16 = rem & 31;
        bSm[r] = SOFF_B + plane * PL_B + krow * SMB_ROW + c16 * 16;
        bKrow[r] = krow; bPlane[r] = plane; bCol[r] = p0 + c16 * 8;
    }

    auto issue = [&](int kc, int buf) {
        uint32_t base = sb + buf * BUFSZ;
        cpasync16(base + aSm, aGp + kc);
#pragma unroll
        for (int r = 0; r < 8; r++) {
            int kg = kc + bKrow[r];
            size_t ch = (kg < K1) ? (aOff1 + kg) : (aOff2 + (kg - K1));
            const __half* src = (bPlane[r] ? g_lo : g_hi)
                              + ch * (size_t)PL + bofs + bCol[r];
            cpasync16(base + bSm[r], src);
        }
        CP_COMMIT();
    };

    const uint32_t offAt = (uint32_t)(lane & 15) * SMA_ROW + (uint32_t)(lane >> 4) * 16
                         + (uint32_t)(wm * 32) * SMA_ROW;
    const uint32_t offBt = (uint32_t)((lane & 7) + ((lane >> 3) & 1) * 8) * SMB_ROW
                         + (uint32_t)(lane >> 4) * 16;

    float acc[2][8][4];
#pragma unroll
    for (int i = 0; i < 2; i++)
#pragma unroll
        for (int j = 0; j < 8; j++)
#pragma unroll
            for (int q = 0; q < 4; q++) acc[i][j][q] = 0.f;

    const int nch = K >> 5;
    issue(0, 0);
    CP_WAIT0();
    __syncthreads();

    for (int c = 0; c < nch; c++) {
        const bool more = (c + 1 < nch);
        if (more) issue((c + 1) * 32, (c + 1) & 1);

        uint32_t base = sb + (c & 1) * BUFSZ;
        uint32_t aH = base + offAt;
        uint32_t bH = base + SOFF_B + offBt, bL = bH + PL_B;
#pragma unroll
        for (int s = 0; s < 2; s++) {
            uint32_t ah[2][4];
#pragma unroll
            for (int i = 0; i < 2; i++)
                ldsm4(ah[i], aH + i * (16 * SMA_ROW) + s * 32);
#pragma unroll
            for (int t = 0; t < 4; t++) {
                uint32_t bh4[4], bl4[4];
                uint32_t bo = s * (16 * SMB_ROW) + (uint32_t)(wn * 64 + t * 16) * 2;
                ldsm4t(bh4, bH + bo);
                ldsm4t(bl4, bL + bo);
#pragma unroll
                for (int jj = 0; jj < 2; jj++) {
                    int j = t * 2 + jj;
                    const uint32_t* bhf = &bh4[jj * 2];
                    const uint32_t* blf = &bl4[jj * 2];
#pragma unroll
                    for (int i = 0; i < 2; i++) {
                        mma16816(acc[i][j], ah[i], bhf);
                        mma16816(acc[i][j], ah[i], blf);
                    }
                }
            }
        }
        if (more) CP_WAIT0();
        __syncthreads();
    }

    EpiArgs ea{e1Off, e2Off, yOff, mode, Chalf, Cout, Yf, E1f, bofs, b};
    const int obase = o0 + wm * 32;
    const int pbase = p0 + wn * 64;
#pragma unroll
    for (int i = 0; i < 2; i++) {
#pragma unroll
        for (int j = 0; j < 8; j++) {
            int oA = obase + i * 16 + g;
            int p  = pbase + j * 8 + tig * 2;
            emitg(ea, oA,     p, acc[i][j][0], acc[i][j][1]);
            emitg(ea, oA + 8, p, acc[i][j][2], acc[i][j][3]);
        }
    }
}

// ---------------- LayerNorm (fp32 in -> hl out) ----------------
__global__ void ln_f32(const float* __restrict__ in, const float* __restrict__ g,
                       const float* __restrict__ be, size_t dstCh)
{
    int b = blockIdx.y;
    int p = blockIdx.x * 256 + threadIdx.x;
    const float* ib = in + (size_t)b * 192 * NP + p;
    float s = 0.f, ss = 0.f;
    for (int c = 0; c < 192; c++) {
        float v = ib[(size_t)c * NP];
        s += v; ss += v * v;
    }
    float mu = s / 192.f;
    float var = ss / 192.f - mu * mu;
    float rstd = rsqrtf(var + 1e-5f);
    size_t ob = dstCh * (size_t)PL + (size_t)b * NP + p;
    for (int c = 0; c < 192; c++) {
        float v = ib[(size_t)c * NP];
        wrhl(ob + (size_t)c * PL, (v - mu) * rstd * g[c] + be[c]);
    }
}
__global__ void ln_hl(size_t srcCh, const float* __restrict__ g,
                      const float* __restrict__ be, size_t dstCh)
{
    int b = blockIdx.y;
    int p = blockIdx.x * 256 + threadIdx.x;
    size_t ibase = srcCh * (size_t)PL + (size_t)b * NP + p;
    float s = 0.f, ss = 0.f;
    for (int c = 0; c < 192; c++) {
        float v = rdhl(ibase + (size_t)c * PL);
        s += v; ss += v * v;
    }
    float mu = s / 192.f;
    float var = ss / 192.f - mu * mu;
    float rstd = rsqrtf(var + 1e-5f);
    size_t ob = dstCh * (size_t)PL + (size_t)b * NP + p;
    for (int c = 0; c < 192; c++) {
        float v = rdhl(ibase + (size_t)c * PL);
        wrhl(ob + (size_t)c * PL, (v - mu) * rstd * g[c] + be[c]);
    }
}

// ---------------- depthwise 3x3 (hl -> hl), smem-tiled ----------------
__global__ void dw_hl(size_t srcCh, const float* __restrict__ w, size_t dstCh, int C)
{
    __shared__ float tile[4][128];
    int b = blockIdx.z, c = blockIdx.y;
    int y0 = blockIdx.x * 2;
    int tr = threadIdx.x >> 7;
    int tx = threadIdx.x & 127;
    size_t ib = (srcCh + c) * (size_t)PL + (size_t)b * NP;
#pragma unroll
    for (int r = tr; r < 4; r += 2) {
        int yy = y0 - 1 + r;
        tile[r][tx] = (yy >= 0 && yy < 128) ? rdhl(ib + yy * 128 + tx) : 0.f;
    }
    __syncthreads();
    const float* wc = w + c * 9;
    float acc = 0.f;
#pragma unroll
    for (int dy = 0; dy < 3; dy++) {
        int r = tr + dy;
#pragma unroll
        for (int dx = -1; dx <= 1; dx++) {
            int xx = tx + dx;
            if (xx < 0 || xx > 127) continue;
            acc = fmaf(tile[r][xx], wc[dy * 3 + dx + 1], acc);
        }
    }
    int y = y0 + tr;
    wrhl((dstCh + c) * (size_t)PL + (size_t)b * NP + y * 128 + tx, acc);
}

// ---------------- row L2 norms of q,k ----------------
__global__ void norm_kernel(float* __restrict__ nrm)
{
    int r = blockIdx.x;              // 0..767
    int b = r / 384, c = r % 384;
    size_t src = (CH_QKV + c) * (size_t)PL + (size_t)b * NP;
    float s = 0.f;
    for (int i = threadIdx.x; i < NP; i += 256) {
        float v = rdhl(src + i);
        s += v * v;
    }
    __shared__ float red[256];
    red[threadIdx.x] = s;
    __syncthreads();
    for (int st = 128; st > 0; st >>= 1) {
        if (threadIdx.x < st) red[threadIdx.x] += red[threadIdx.x + st];
        __syncthreads();
    }
    if (threadIdx.x == 0) nrm[r] = fmaxf(sqrtf(red[0]), 1e-12f);
}

// ---------------- attention scores ----------------
__global__ void scores_kernel(float* __restrict__ S)
{
    int bh = blockIdx.x;
    int ks = blockIdx.y;
    int b = bh / 6, h = bh % 6;
    size_t qb = (CH_QKV + h * 32) * (size_t)PL + (size_t)b * NP;
    size_t kb = (CH_QKV + 192 + h * 32) * (size_t)PL + (size_t)b * NP;
    __shared__ float qs[32][65], ksm[32][65];
    int tid = threadIdx.x;
    int c = tid >> 3, d0 = (tid & 7) * 4;
    float acc[4] = {0.f, 0.f, 0.f, 0.f};
    int kbase = ks * (NP / KSPLIT);
    for (int t = 0; t < (NP / KSPLIT) / 64; t++) {
        int k0 = kbase + t * 64;
#pragma unroll
        for (int i = 0; i < 8; i++) {
            int e = tid + i * 256;
            int row = e >> 6, col = e & 63;
            qs[row][col]  = rdhl(qb + (size_t)row * PL + k0 + col);
            ksm[row][col] = rdhl(kb + (size_t)row * PL + k0 + col);
        }
        __syncthreads();
#pragma unroll
        for (int kk = 0; kk < 64; kk++) {
            float qv = qs[c][kk];
#pragma unroll
            for (int j = 0; j < 4; j++)
                acc[j] = fmaf(qv, ksm[d0 + j][kk], acc[j]);
        }
        __syncthreads();
    }
    float* Sp = S + (size_t)ks * 12288 + bh * 1024 + c * 32 + d0;
#pragma unroll
    for (int j = 0; j < 4; j++) Sp[j] = acc[j];
}

// ---------------- softmax with norm + temperature ----------------
__global__ void softmax_kernel(float* __restrict__ S, const float* __restrict__ nrm,
                               const float* __restrict__ temp)
{
    int bh = blockIdx.y;
    int c  = blockIdx.x;
    int b = bh / 6, h = bh % 6;
    int d = threadIdx.x;
    float acc = 0.f;
    size_t idx = (size_t)bh * 1024 + c * 32 + d;
    for (int j = 0; j < KSPLIT; j++) acc += S[(size_t)j * 12288 + idx];
    float nq = nrm[b * 384 + h * 32 + c];
    float nk = nrm[b * 384 + 192 + h * 32 + d];
    float v = acc / (nq * nk) * temp[h];
    float m = v;
    for (int o = 16; o; o >>= 1) m = fmaxf(m, __shfl_xor_sync(0xffffffffu, m, o));
    float e = expf(v - m);
    float s = e;
    for (int o = 16; o; o >>= 1) s += __shfl_xor_sync(0xffffffffu, s, o);
    S[idx] = e / s;
}

// ---------------- out = attn @ v (hl in, hl out) ----------------
__global__ void av_kernel(const float* __restrict__ S)
{
    int b = blockIdx.z, h = blockIdx.y;
    int p = blockIdx.x * 128 + threadIdx.x;
    __shared__ float A[32][32];
    int bh = b * 6 + h;
    for (int i = threadIdx.x; i < 1024; i += 128)
        A[i >> 5][i & 31] = S[(size_t)bh * 1024 + i];
    __syncthreads();
    size_t vb = (CH_QKV + 384 + h * 32) * (size_t)PL + (size_t)b * NP + p;
    float vr[32];
#pragma unroll
    for (int d = 0; d < 32; d++) vr[d] = rdhl(vb + (size_t)d * PL);
    size_t ob = (CH_OUTA + h * 32) * (size_t)PL + (size_t)b * NP + p;
#pragma unroll
    for (int c = 0; c < 32; c++) {
        float acc = 0.f;
#pragma unroll
        for (int d = 0; d < 32; d++) acc = fmaf(A[c][d], vr[d], acc);
        wrhl(ob + (size_t)c * PL, acc);
    }
}

// ---------------- host orchestration ----------------
static inline void launch_gemm(size_t wOff, int K, size_t aOff1, int K1, size_t aOff2,
                               int Cout, size_t e1Off, size_t e2Off, size_t yOff,
                               int mode, int Chalf, float* Yf,
                               const float* E1f = nullptr)
{
    dim3 grid(NP / 256, Cout / 64, NB);
    hmma_gemm<<<grid, 256, GSMEM>>>(wOff, K, aOff1, K1, aOff2, Cout,
                                    e1Off, e2Off, yOff, mode, Chalf, Yf, E1f);
}

extern "C" void kernel_launch(void* const* d_in, const int* in_sizes, int n_in,
                              void* d_out, int out_size)
{
    const float* x       = (const float*)d_in[0];
    const float* feature = (const float*)d_in[1];
    const float* nf_w = (const float*)d_in[2];
    const float* nf_b = (const float*)d_in[3];
    const float* n1_w = (const float*)d_in[4];
    const float* n1_b = (const float*)d_in[5];
    const float* n2_w = (const float*)d_in[6];
    const float* n2_b = (const float*)d_in[7];
    const float* a_cc_w   = (const float*)d_in[8];
    const float* a_fus_w  = (const float*)d_in[9];
    const float* a_msk_w  = (const float*)d_in[10];
    const float* a_qkv_w  = (const float*)d_in[11];
    const float* a_qkvdw  = (const float*)d_in[12];
    const float* a_temp   = (const float*)d_in[13];
    const float* a_proj_w = (const float*)d_in[14];
    const float* f_pm_w   = (const float*)d_in[15];
    const float* f_pi_w   = (const float*)d_in[16];
    const float* f_dw_w   = (const float*)d_in[17];
    const float* f_cc_w   = (const float*)d_in[18];
    const float* f_fus_w  = (const float*)d_in[19];
    const float* f_msk_w  = (const float*)d_in[20];
    const float* f_po_w   = (const float*)d_in[21];
    float* out = (float*)d_out;

    cudaFuncSetAttribute(hmma_gemm, cudaFuncAttributeMaxDynamicSharedMemorySize, GSMEM);

    float* f32 = nullptr;
    cudaGetSymbolAddress((void**)&f32, g_f32);
    float* NRM = f32;
    float* S   = f32 + 1024;

    auto cw = [&](const float* src, size_t off, int n) {
        cvt_w<<<(n + 255) / 256, 256>>>(src, off, n);
    };
    cw(a_msk_w,  WO_AMSK,  36864);
    cw(a_cc_w,   WO_ACC,   147456);
    cw(a_fus_w,  WO_AFUS,  73728);
    cw(a_qkv_w,  WO_AQKV,  110592);
    cw(a_proj_w, WO_APROJ, 36864);
    cw(f_pm_w,   WO_FPM,   110592);
    cw(f_pi_w,   WO_FPI,   221184);
    cw(f_msk_w,  WO_FMSK,  331776);
    cw(f_cc_w,   WO_FCC,   1327104);
    cw(f_fus_w,  WO_FFUS,  663552);
    cw(f_po_w,   WO_FPO,   110592);

    dim3 lng(NP / 256, NB);
    ln_f32<<<lng, 256>>>(feature, nf_w, nf_b, CH_F);
    ln_f32<<<lng, 256>>>(x, n1_w, n1_b, CH_X1);

    // --- attention DDF ---
    launch_gemm(WO_AMSK, 192, CH_F, 192, CH_F, 192, 0, 0, CH_MT, 0, 0, nullptr);
    launch_gemm(WO_ACC, 384, CH_X1, 192, CH_MT, 384, CH_X1, CH_MT, CH_OUTD, 2, 192, nullptr);
    launch_gemm(WO_AFUS, 384, CH_OUTD, 384, CH_OUTD, 192, CH_X1, 0, CH_ATTIN, 1, 0, nullptr);

    // qkv + depthwise
    launch_gemm(WO_AQKV, 192, CH_ATTIN, 192, CH_ATTIN, 576, 0, 0, CH_QKV0, 0, 0, nullptr);
    dw_hl<<<dim3(64, 576, NB), 256>>>(CH_QKV0, a_qkvdw, CH_QKV, 576);

    // channel attention
    norm_kernel<<<768, 256>>>(NRM);
    scores_kernel<<<dim3(12, KSPLIT), 256>>>(S);
    softmax_kernel<<<dim3(32, 12), 32>>>(S, NRM, a_temp);
    av_kernel<<<dim3(NP / 128, 6, NB), 128>>>(S);

    // proj + residual with original fp32 x (read directly in epilogue)
    launch_gemm(WO_APROJ, 192, CH_OUTA, 192, CH_OUTA, 192, 0, 0, CH_XMID, 1, 0,
                nullptr, x);

    // --- FFN ---
    ln_hl<<<lng, 256>>>(CH_XMID, n2_w, n2_b, CH_X2L);
    launch_gemm(WO_FPM, 192, CH_F, 192, CH_F, 576, 0, 0, CH_FM, 0, 0, nullptr);
    launch_gemm(WO_FPI, 192, CH_X2L, 192, CH_X2L, 1152, 0, 0, CH_XIN, 0, 0, nullptr);
    dw_hl<<<dim3(64, 1152, NB), 256>>>(CH_XIN, f_dw_w, CH_DW, 1152);

    launch_gemm(WO_FMSK, 576, CH_FM, 576, CH_FM, 576, 0, 0, CH_MT2, 0, 0, nullptr);
    launch_gemm(WO_FCC, 1152, CH_X2H, 576, CH_MT2, 1152, CH_X2H, CH_MT2, CH_OUT2, 2, 576, nullptr);
    launch_gemm(WO_FFUS, 1152, CH_OUT2, 1152, CH_OUT2, 576, CH_X2H, CH_DW, CH_GX, 3, 0, nullptr);
    launch_gemm(WO_FPO, 576, CH_GX, 576, CH_GX, 192, CH_XMID, 0, 0, 1, 0, out);
}